// round 8
// baseline (speedup 1.0000x reference)
#include <cuda_runtime.h>
#include <cstdint>
#include <math.h>
#include <mma.h>

using namespace nvcuda;

#define BATCH 512
#define HEADS 4
#define SDIM  256
#define PPIX  196
#define DH    64
#define PD    (PPIX * DH)
#define NPAD  208
#define NTILES 1568            // 100352 / 64

// ---------------- scratch ----------------
#define QKV_ELEMS (BATCH * HEADS * PPIX * DH)
__device__ float g_q[QKV_ELEMS];
__device__ float g_k[QKV_ELEMS];
__device__ float g_v[QKV_ELEMS];
__device__ float g_av[BATCH * PPIX * SDIM];   // flat: [g][c], g = b*196+p

__device__ __forceinline__ float f2tf(float v) {
    uint32_t u;
    asm("cvt.rna.tf32.f32 %0, %1;" : "=r"(u) : "f"(v));
    return __uint_as_float(u);
}

__device__ __forceinline__ void cpg16z(float* dst, const float* src, int bytes) {
    uint32_t d = (uint32_t)__cvta_generic_to_shared(dst);
    asm volatile("cp.async.cg.shared.global [%0], [%1], 16, %2;"
                 :: "r"(d), "l"(src), "r"(bytes) : "memory");
}
#define CP_COMMIT() asm volatile("cp.async.commit_group;" ::: "memory")
#define CP_WAIT(n)  asm volatile("cp.async.wait_group %0;" :: "n"(n) : "memory")

typedef wmma::fragment<wmma::matrix_a, 16, 16, 8, wmma::precision::tf32, wmma::row_major> FragA;
typedef wmma::fragment<wmma::matrix_b, 16, 16, 8, wmma::precision::tf32, wmma::row_major> FragBR;
typedef wmma::fragment<wmma::matrix_b, 16, 16, 8, wmma::precision::tf32, wmma::col_major> FragBC;
typedef wmma::fragment<wmma::accumulator, 16, 16, 8, float> FragC;

// ============================================================================
// Kernel 1: QKV projection, global-N GEMM (zero padding).
// D[o, g] = W[o,:]·xcol(g) + bias[o], g = b*196+p. CTA 128(M) x 64(N).
// grid = (1568, 6): y = ws*2 + mtile. Reg-staged dbuf, K chunks of 32.
// ============================================================================
#define QST 6912   // stage floats: A 128x36 = 4608 | B 32x72 = 2304

__global__ void __launch_bounds__(256, 2)
qkv_tc(const float* __restrict__ x,
       const float* __restrict__ wq, const float* __restrict__ bq,
       const float* __restrict__ wk, const float* __restrict__ bk,
       const float* __restrict__ wv, const float* __restrict__ bv)
{
    extern __shared__ float sm[];
    const int tid = threadIdx.x;
    const int w   = tid >> 5;
    const int n0  = blockIdx.x * 64;
    const int ws  = blockIdx.y >> 1;
    const int m0  = (blockIdx.y & 1) * 128;

    const float* W    = (ws == 0) ? wq : (ws == 1) ? wk : wv;
    const float* bias = (ws == 0) ? bq : (ws == 1) ? bk : bv;
    float* Og         = (ws == 0) ? g_q : (ws == 1) ? g_k : g_v;

    const int wm = (w >> 1) * 32;
    const int wn = (w & 1) * 32;

    // A-fill: 128x32 over 4 passes. B-fill: 32x64 over 2 passes of 16 rows.
    const int ar = tid >> 3,  ac = (tid & 7) * 4;
    const int br = tid >> 4,  bc = (tid & 15) * 4;
    const int g0   = n0 + bc;
    const int b0c  = g0 / PPIX;
    const int p0c  = g0 - b0c * PPIX;
    const bool cross = (p0c > PPIX - 4);     // float4 spans batch boundary
    const float* xb0 = x + (size_t)b0c * (SDIM * PPIX) + p0c;

    FragC acc[2][2];
    #pragma unroll
    for (int i = 0; i < 2; i++)
        #pragma unroll
        for (int j = 0; j < 2; j++) wmma::fill_fragment(acc[i][j], 0.f);

    float ra[16], rb[8];

    #define QKV_LOAD(k0) do {                                                     \
        _Pragma("unroll")                                                         \
        for (int t = 0; t < 4; t++) {                                             \
            float4 v = *(const float4*)(W + (size_t)(m0 + ar + t * 32) * SDIM     \
                                          + (k0) + ac);                           \
            ra[t*4+0]=v.x; ra[t*4+1]=v.y; ra[t*4+2]=v.z; ra[t*4+3]=v.w;           \
        }                                                                         \
        _Pragma("unroll")                                                         \
        for (int t = 0; t < 2; t++) {                                             \
            int krow = (k0) + br + t * 16;                                        \
            if (!cross) {                                                         \
                float4 v = *(const float4*)(xb0 + (size_t)krow * PPIX);           \
                rb[t*4+0]=v.x; rb[t*4+1]=v.y; rb[t*4+2]=v.z; rb[t*4+3]=v.w;       \
            } else {                                                              \
                _Pragma("unroll")                                                 \
                for (int e = 0; e < 4; e++) {                                     \
                    int g = g0 + e;                                               \
                    int bb = g / PPIX, pp = g - bb * PPIX;                        \
                    rb[t*4+e] = x[((size_t)bb * SDIM + krow) * PPIX + pp];        \
                }                                                                 \
            }                                                                     \
        }                                                                         \
    } while (0)

    #define QKV_STORE(s) do {                                                    \
        float* A_ = sm + (s) * QST;                                               \
        float* B_ = A_ + 4608;                                                    \
        _Pragma("unroll")                                                         \
        for (int t = 0; t < 4; t++) {                                             \
            float4 v = make_float4(f2tf(ra[t*4+0]), f2tf(ra[t*4+1]),              \
                                   f2tf(ra[t*4+2]), f2tf(ra[t*4+3]));             \
            *(float4*)(A_ + (ar + t * 32) * 36 + ac) = v;                         \
        }                                                                         \
        _Pragma("unroll")                                                         \
        for (int t = 0; t < 2; t++) {                                             \
            float4 v = make_float4(f2tf(rb[t*4+0]), f2tf(rb[t*4+1]),              \
                                   f2tf(rb[t*4+2]), f2tf(rb[t*4+3]));             \
            *(float4*)(B_ + (br + t * 16) * 72 + bc) = v;                         \
        }                                                                         \
    } while (0)

    QKV_LOAD(0);
    QKV_STORE(0);
    __syncthreads();

    #pragma unroll
    for (int ch = 0; ch < 8; ch++) {
        if (ch < 7) QKV_LOAD((ch + 1) * 32);

        const float* cA = sm + (ch & 1) * QST;
        const float* cB = cA + 4608;
        #pragma unroll
        for (int kk = 0; kk < 32; kk += 8) {
            FragA a0, a1;
            wmma::load_matrix_sync(a0, cA + wm * 36 + kk, 36);
            wmma::load_matrix_sync(a1, cA + (wm + 16) * 36 + kk, 36);
            FragBR b0, b1;
            wmma::load_matrix_sync(b0, cB + kk * 72 + wn, 72);
            wmma::load_matrix_sync(b1, cB + kk * 72 + wn + 16, 72);
            wmma::mma_sync(acc[0][0], a0, b0, acc[0][0]);
            wmma::mma_sync(acc[0][1], a0, b1, acc[0][1]);
            wmma::mma_sync(acc[1][0], a1, b0, acc[1][0]);
            wmma::mma_sync(acc[1][1], a1, b1, acc[1][1]);
        }

        if (ch < 7) QKV_STORE((ch + 1) & 1);
        __syncthreads();
    }

    // epilogue (reuse smem as C, ld 68)
    float* sC = sm;
    #pragma unroll
    for (int i = 0; i < 2; i++)
        #pragma unroll
        for (int j = 0; j < 2; j++)
            wmma::store_matrix_sync(sC + (wm + i * 16) * 68 + wn + j * 16,
                                    acc[i][j], 68, wmma::mem_row_major);
    __syncthreads();

    const int m = tid & 127;
    const int half = tid >> 7;
    const int o = m0 + m;
    const int h = o >> 6, d = o & 63;
    const float bb = bias[o];
    int gg = n0 + half * 32;
    int bcur = gg / PPIX;
    int pcur = gg - bcur * PPIX;
    #pragma unroll
    for (int i = 0; i < 32; i++) {
        Og[(((size_t)bcur * HEADS + h) * PPIX + pcur) * DH + d] =
            sC[m * 68 + half * 32 + i] + bb;
        if (++pcur == PPIX) { pcur = 0; bcur++; }
    }
}

// ============================================================================
// Kernel 2: attention, 32-row q-tiles, smem-cvt (no per-fragment cvt).
// grid = (7, HEADS, BATCH). smem floats: Q 2304 | S 6912 | KV 14976 | sum 32
// ============================================================================
#define ATQ   0
#define ATS   2304
#define ATKV  9216
#define ATSUM 24192
#define ATTOT 24224

__global__ void __launch_bounds__(512, 2)
attn_tc()
{
    extern __shared__ float sm[];
    const int tid = threadIdx.x;
    const int w   = tid >> 5;
    const int b  = blockIdx.z;
    const int h  = blockIdx.y;
    const int q0 = blockIdx.x * 32;
    const int mrows = (q0 == 192) ? 16 : 32;

    const size_t bh = (size_t)b * HEADS + h;
    const float* Qg = g_q + bh * PD;
    const float* Kg = g_k + bh * PD;
    const float* Vg = g_v + bh * PD;

    // issue K + Q (raw fp32)
    for (int idx = tid; idx < NPAD * 16; idx += 512) {
        int r = idx >> 4, c = (idx & 15) * 4;
        int rs = r < PPIX ? r : 0;
        cpg16z(sm + ATKV + r * 72 + c, Kg + (size_t)rs * DH + c, r < PPIX ? 16 : 0);
    }
    for (int idx = tid; idx < 32 * 16; idx += 512) {
        int r = idx >> 4, c = (idx & 15) * 4;
        int gq = q0 + r;
        int rs = gq < PPIX ? gq : 0;
        cpg16z(sm + ATQ + r * 72 + c, Qg + (size_t)rs * DH + c, gq < PPIX ? 16 : 0);
    }
    CP_COMMIT();
    CP_WAIT(0);
    __syncthreads();

    // cvt K and Q in smem once (float4 passes)
    for (int idx = tid; idx < (NPAD + 32) * 16; idx += 512) {
        int r = idx >> 4, c4 = (idx & 15) * 4;
        float* ptr = sm + (r < NPAD ? ATKV + r * 72 : ATQ + (r - NPAD) * 72) + c4;
        float4 v = *(float4*)ptr;
        *(float4*)ptr = make_float4(f2tf(v.x), f2tf(v.y), f2tf(v.z), f2tf(v.w));
    }
    __syncthreads();

    // ---- phase A: S = Q K^T (raw scores; scale folded into softmax) ----
    {
        const int wm = (w >> 3) * 16;
        if (wm < mrows) {
            const int g = w & 7;
            const int cnt   = (g < 5) ? 2 : 1;
            const int jbase = (g < 5) ? g * 2 : 5 + g;
            FragC acc[2];
            wmma::fill_fragment(acc[0], 0.f);
            wmma::fill_fragment(acc[1], 0.f);
            #pragma unroll
            for (int kk = 0; kk < 64; kk += 8) {
                FragA a;
                wmma::load_matrix_sync(a, sm + ATQ + wm * 72 + kk, 72);
                for (int q = 0; q < cnt; q++) {
                    FragBC bf;
                    wmma::load_matrix_sync(bf, sm + ATKV + (jbase + q) * 16 * 72 + kk, 72);
                    wmma::mma_sync(acc[q], a, bf, acc[q]);
                }
            }
            for (int q = 0; q < cnt; q++)
                wmma::store_matrix_sync(sm + ATS + wm * 216 + (jbase + q) * 16,
                                        acc[q], 216, wmma::mem_row_major);
        }
    }
    __syncthreads();

    // issue V (overwrites K) — overlaps softmax
    for (int idx = tid; idx < NPAD * 16; idx += 512) {
        int r = idx >> 4, c = (idx & 15) * 4;
        int rs = r < PPIX ? r : 0;
        cpg16z(sm + ATKV + r * 72 + c, Vg + (size_t)rs * DH + c, r < PPIX ? 16 : 0);
    }
    CP_COMMIT();

    // ---- softmax (16 lanes per row; exp output rounded to tf32) ----
    {
        int row = tid >> 4, jl = tid & 15;
        if (row < mrows) {
            float* srow = sm + ATS + row * 216;
            float m = -1e30f;
            for (int c = jl; c < PPIX; c += 16) m = fmaxf(m, srow[c]);
            m = fmaxf(m, __shfl_xor_sync(0xffffffffu, m, 1));
            m = fmaxf(m, __shfl_xor_sync(0xffffffffu, m, 2));
            m = fmaxf(m, __shfl_xor_sync(0xffffffffu, m, 4));
            m = fmaxf(m, __shfl_xor_sync(0xffffffffu, m, 8));
            float s = 0.f;
            for (int c = jl; c < NPAD; c += 16) {
                float e = (c < PPIX) ? f2tf(__expf((srow[c] - m) * 0.125f)) : 0.f;
                srow[c] = e;
                s += e;
            }
            s += __shfl_xor_sync(0xffffffffu, s, 1);
            s += __shfl_xor_sync(0xffffffffu, s, 2);
            s += __shfl_xor_sync(0xffffffffu, s, 4);
            s += __shfl_xor_sync(0xffffffffu, s, 8);
            if (jl == 0) sm[ATSUM + row] = s;
        }
    }
    CP_WAIT(0);
    __syncthreads();

    // cvt V in smem
    for (int idx = tid; idx < NPAD * 16; idx += 512) {
        int r = idx >> 4, c4 = (idx & 15) * 4;
        float* ptr = sm + ATKV + r * 72 + c4;
        float4 v = *(float4*)ptr;
        *(float4*)ptr = make_float4(f2tf(v.x), f2tf(v.y), f2tf(v.z), f2tf(v.w));
    }
    __syncthreads();

    // ---- phase C: AV = P V; 16 warps = 2(wm) x 4(wn16) x 2(K half) ----
    {
        const int kh = w >> 3;
        const int r2 = w & 7;
        const int wm = (r2 >> 2) * 16;
        const int wn = (r2 & 3) * 16;
        const bool act = (wm < mrows);
        FragC acc;
        wmma::fill_fragment(acc, 0.f);
        if (act) {
            #pragma unroll
            for (int s = 0; s < 13; s++) {
                int k = kh * 104 + s * 8;
                FragA a;
                wmma::load_matrix_sync(a, sm + ATS + wm * 216 + k, 216);
                FragBR bf;
                wmma::load_matrix_sync(bf, sm + ATKV + k * 72 + wn, 72);
                wmma::mma_sync(acc, a, bf, acc);
            }
        }
        __syncthreads();   // all V reads done before partials overwrite buffers
        if (act) {
            float* buf = sm + (kh ? ATKV : ATQ);
            wmma::store_matrix_sync(buf + wm * 72 + wn, acc, 72, wmma::mem_row_major);
        }
    }
    __syncthreads();

    // epilogue: normalize, write flat av [g][h*64+d]
    float* avb = g_av + (size_t)b * (PPIX * SDIM);
    const int d = tid & 63;
    #pragma unroll
    for (int r = 0; r < 4; r++) {
        int q = (tid >> 6) + r * 8;
        int gq = q0 + q;
        if (gq < PPIX) {
            float inv = 1.f / sm[ATSUM + q];
            avb[(size_t)h * PD + (size_t)gq * DH + d] =
                (sm[ATQ + q * 72 + d] + sm[ATKV + q * 72 + d]) * inv;
        }
    }
}

// ============================================================================
// Kernel 3: output projection, global-N (zero padding).
// out[b,o,p] = bo[o] + sum_c wo[o,c] * g_av[g][c], g = b*196+p.
// CTA 128(M) x 64(N). grid = (1568, 2).
// ============================================================================
#define OST 7168   // stage floats: A 128x36 = 4608 | B 64x40 = 2560

__global__ void __launch_bounds__(256, 2)
outproj_tc(const float* __restrict__ wo, const float* __restrict__ bo,
           float* __restrict__ out)
{
    extern __shared__ float sm[];
    const int tid = threadIdx.x;
    const int w   = tid >> 5;
    const int n0  = blockIdx.x * 64;
    const int m0  = blockIdx.y * 128;

    const int wm = (w >> 1) * 32;
    const int wn = (w & 1) * 32;

    const int ar = tid >> 3, ac = (tid & 7) * 4;
    const int br = tid >> 3, bc = (tid & 7) * 4;
    const float* avrow = g_av + (size_t)(n0 + br) * SDIM + bc;   // row g of B

    FragC acc[2][2];
    #pragma unroll
    for (int i = 0; i < 2; i++)
        #pragma unroll
        for (int j = 0; j < 2; j++) wmma::fill_fragment(acc[i][j], 0.f);

    float ra[16], rb[8];

    #define OUT_LOAD(k0) do {                                                     \
        _Pragma("unroll")                                                         \
        for (int t = 0; t < 4; t++) {                                             \
            float4 v = *(const float4*)(wo + (size_t)(m0 + ar + t * 32) * SDIM    \
                                           + (k0) + ac);                          \
            ra[t*4+0]=v.x; ra[t*4+1]=v.y; ra[t*4+2]=v.z; ra[t*4+3]=v.w;           \
        }                                                                         \
        _Pragma("unroll")                                                         \
        for (int t = 0; t < 2; t++) {                                             \
            float4 v = *(const float4*)(avrow + (size_t)t * 32 * SDIM + (k0));    \
            rb[t*4+0]=v.x; rb[t*4+1]=v.y; rb[t*4+2]=v.z; rb[t*4+3]=v.w;           \
        }                                                                         \
    } while (0)

    #define OUT_STORE(s) do {                                                    \
        float* A_ = sm + (s) * OST;                                               \
        float* B_ = A_ + 4608;                                                    \
        _Pragma("unroll")                                                         \
        for (int t = 0; t < 4; t++) {                                             \
            float4 v = make_float4(f2tf(ra[t*4+0]), f2tf(ra[t*4+1]),              \
                                   f2tf(ra[t*4+2]), f2tf(ra[t*4+3]));             \
            *(float4*)(A_ + (ar + t * 32) * 36 + ac) = v;                         \
        }                                                                         \
        _Pragma("unroll")                                                         \
        for (int t = 0; t < 2; t++) {                                             \
            float4 v = make_float4(f2tf(rb[t*4+0]), f2tf(rb[t*4+1]),              \
                                   f2tf(rb[t*4+2]), f2tf(rb[t*4+3]));             \
            *(float4*)(B_ + (br + t * 32) * 40 + bc) = v;                         \
        }                                                                         \
    } while (0)

    OUT_LOAD(0);
    OUT_STORE(0);
    __syncthreads();

    #pragma unroll
    for (int ch = 0; ch < 8; ch++) {
        if (ch < 7) OUT_LOAD((ch + 1) * 32);

        const float* cA = sm + (ch & 1) * OST;
        const float* cB = cA + 4608;
        #pragma unroll
        for (int kk = 0; kk < 32; kk += 8) {
            FragA a0, a1;
            wmma::load_matrix_sync(a0, cA + wm * 36 + kk, 36);
            wmma::load_matrix_sync(a1, cA + (wm + 16) * 36 + kk, 36);
            FragBC b0, b1;
            wmma::load_matrix_sync(b0, cB + wn * 40 + kk, 40);
            wmma::load_matrix_sync(b1, cB + (wn + 16) * 40 + kk, 40);
            wmma::mma_sync(acc[0][0], a0, b0, acc[0][0]);
            wmma::mma_sync(acc[0][1], a0, b1, acc[0][1]);
            wmma::mma_sync(acc[1][0], a1, b0, acc[1][0]);
            wmma::mma_sync(acc[1][1], a1, b1, acc[1][1]);
        }

        if (ch < 7) OUT_STORE((ch + 1) & 1);
        __syncthreads();
    }

    float* sC = sm;
    #pragma unroll
    for (int i = 0; i < 2; i++)
        #pragma unroll
        for (int j = 0; j < 2; j++)
            wmma::store_matrix_sync(sC + (wm + i * 16) * 68 + wn + j * 16,
                                    acc[i][j], 68, wmma::mem_row_major);
    __syncthreads();

    const int m = tid >> 1;
    const int half = tid & 1;
    const int o = m0 + m;
    const float bb = bo[o];
    int gg = n0 + half * 32;
    int bcur = gg / PPIX;
    int pcur = gg - bcur * PPIX;
    #pragma unroll
    for (int i = 0; i < 32; i++) {
        out[((size_t)bcur * SDIM + o) * PPIX + pcur] =
            sC[m * 68 + half * 32 + i] + bb;
        if (++pcur == PPIX) { pcur = 0; bcur++; }
    }
}

// ============================================================================
extern "C" void kernel_launch(void* const* d_in, const int* in_sizes, int n_in,
                              void* d_out, int out_size)
{
    const float* x  = (const float*)d_in[0];
    const float* wq = (const float*)d_in[1];
    const float* bq = (const float*)d_in[2];
    const float* wk = (const float*)d_in[3];
    const float* bk = (const float*)d_in[4];
    const float* wv = (const float*)d_in[5];
    const float* bv = (const float*)d_in[6];
    const float* wo = (const float*)d_in[7];
    const float* bo = (const float*)d_in[8];
    float* out = (float*)d_out;

    const int qkv_smem = 2 * QST * 4;           // 55,296
    cudaFuncSetAttribute(qkv_tc, cudaFuncAttributeMaxDynamicSharedMemorySize, qkv_smem);
    qkv_tc<<<dim3(NTILES, 6), 256, qkv_smem>>>(x, wq, bq, wk, bk, wv, bv);

    const int attn_smem = ATTOT * 4;            // 96,896
    cudaFuncSetAttribute(attn_tc, cudaFuncAttributeMaxDynamicSharedMemorySize, attn_smem);
    attn_tc<<<dim3(7, HEADS, BATCH), 512, attn_smem>>>();

    const int out_smem = 2 * OST * 4;           // 57,344
    cudaFuncSetAttribute(outproj_tc, cudaFuncAttributeMaxDynamicSharedMemorySize, out_smem);
    outproj_tc<<<dim3(NTILES, 2), 256, out_smem>>>(wo, bo, out);
}

// round 9
// speedup vs baseline: 1.0851x; 1.0851x over previous
#include <cuda_runtime.h>
#include <cstdint>
#include <math.h>
#include <mma.h>

using namespace nvcuda;

#define BATCH 512
#define HEADS 4
#define SDIM  256
#define PPIX  196
#define DH    64
#define PD    (PPIX * DH)
#define NPAD  208
#define NTILES 1568            // 100352 / 64

// ---------------- scratch ----------------
#define QKV_ELEMS (BATCH * HEADS * PPIX * DH)
__device__ float g_q[QKV_ELEMS];
__device__ float g_k[QKV_ELEMS];
__device__ float g_v[QKV_ELEMS];
__device__ float g_av[BATCH * PPIX * SDIM];   // flat [g][c], tf32-valued
__device__ float g_wc[4][SDIM * SDIM];        // tf32-rounded wq,wk,wv,wo

__device__ __forceinline__ float f2tf(float v) {
    uint32_t u;
    asm("cvt.rna.tf32.f32 %0, %1;" : "=r"(u) : "f"(v));
    return __uint_as_float(u);
}

__device__ __forceinline__ void cpa16(float* dst, const float* src) {
    uint32_t d = (uint32_t)__cvta_generic_to_shared(dst);
    asm volatile("cp.async.cg.shared.global [%0], [%1], 16;" :: "r"(d), "l"(src) : "memory");
}
__device__ __forceinline__ void cpg16z(float* dst, const float* src, int bytes) {
    uint32_t d = (uint32_t)__cvta_generic_to_shared(dst);
    asm volatile("cp.async.cg.shared.global [%0], [%1], 16, %2;"
                 :: "r"(d), "l"(src), "r"(bytes) : "memory");
}
#define CP_COMMIT() asm volatile("cp.async.commit_group;" ::: "memory")
#define CP_WAIT(n)  asm volatile("cp.async.wait_group %0;" :: "n"(n) : "memory")

typedef wmma::fragment<wmma::matrix_a, 16, 16, 8, wmma::precision::tf32, wmma::row_major> FragA;
typedef wmma::fragment<wmma::matrix_b, 16, 16, 8, wmma::precision::tf32, wmma::row_major> FragBR;
typedef wmma::fragment<wmma::matrix_b, 16, 16, 8, wmma::precision::tf32, wmma::col_major> FragBC;
typedef wmma::fragment<wmma::accumulator, 16, 16, 8, float> FragC;

// ============================================================================
// Kernel 0: round weights to tf32 once.
// ============================================================================
__global__ void cvt_w(const float* __restrict__ wq, const float* __restrict__ wk,
                      const float* __restrict__ wv, const float* __restrict__ wo)
{
    int i = blockIdx.x * 256 + threadIdx.x;
    g_wc[0][i] = f2tf(wq[i]);
    g_wc[1][i] = f2tf(wk[i]);
    g_wc[2][i] = f2tf(wv[i]);
    g_wc[3][i] = f2tf(wo[i]);
}

// ============================================================================
// Kernel 1: QKV projection, global-N. CTA 128(M) x 64(N). grid (1568, 6).
// A via cp.async (pre-rounded weights); B reg-staged (x needs cvt).
// stage floats: A 128x36 = 4608 | B 32x72 = 2304 -> 6912
// ============================================================================
#define QST 6912

__global__ void __launch_bounds__(256, 2)
qkv_tc(const float* __restrict__ x,
       const float* __restrict__ bq, const float* __restrict__ bk,
       const float* __restrict__ bv)
{
    extern __shared__ float sm[];
    const int tid = threadIdx.x;
    const int w   = tid >> 5;
    const int n0  = blockIdx.x * 64;
    const int ws  = blockIdx.y >> 1;
    const int m0  = (blockIdx.y & 1) * 128;

    const float* W    = g_wc[ws];
    const float* bias = (ws == 0) ? bq : (ws == 1) ? bk : bv;
    float* Og         = (ws == 0) ? g_q : (ws == 1) ? g_k : g_v;

    const int wm = (w >> 1) * 32;
    const int wn = (w & 1) * 32;

    const int ar = tid >> 3,  ac = (tid & 7) * 4;     // A: 4 passes of 32 rows
    const int br = tid >> 4,  bc = (tid & 15) * 4;    // B: 2 passes of 16 rows
    const int g0   = n0 + bc;
    const int b0c  = g0 / PPIX;
    const int p0c  = g0 - b0c * PPIX;
    const bool cross = (p0c > PPIX - 4);
    const float* xb0 = x + (size_t)b0c * (SDIM * PPIX) + p0c;

    FragC acc[2][2];
    #pragma unroll
    for (int i = 0; i < 2; i++)
        #pragma unroll
        for (int j = 0; j < 2; j++) wmma::fill_fragment(acc[i][j], 0.f);

    float rb[8];

    #define QKV_ISSUE_A(s, k0) do {                                               \
        float* A_ = sm + (s) * QST;                                               \
        _Pragma("unroll")                                                         \
        for (int t = 0; t < 4; t++)                                               \
            cpa16(A_ + (ar + t * 32) * 36 + ac,                                   \
                  W + (size_t)(m0 + ar + t * 32) * SDIM + (k0) + ac);             \
        CP_COMMIT();                                                              \
    } while (0)

    #define QKV_LOAD_B(k0) do {                                                   \
        _Pragma("unroll")                                                         \
        for (int t = 0; t < 2; t++) {                                             \
            int krow = (k0) + br + t * 16;                                        \
            if (!cross) {                                                         \
                float4 v = *(const float4*)(xb0 + (size_t)krow * PPIX);           \
                rb[t*4+0]=v.x; rb[t*4+1]=v.y; rb[t*4+2]=v.z; rb[t*4+3]=v.w;       \
            } else {                                                              \
                _Pragma("unroll")                                                 \
                for (int e = 0; e < 4; e++) {                                     \
                    int g = g0 + e;                                               \
                    int bb = g / PPIX, pp = g - bb * PPIX;                        \
                    rb[t*4+e] = x[((size_t)bb * SDIM + krow) * PPIX + pp];        \
                }                                                                 \
            }                                                                     \
        }                                                                         \
    } while (0)

    #define QKV_STORE_B(s) do {                                                  \
        float* B_ = sm + (s) * QST + 4608;                                        \
        _Pragma("unroll")                                                         \
        for (int t = 0; t < 2; t++) {                                             \
            float4 v = make_float4(f2tf(rb[t*4+0]), f2tf(rb[t*4+1]),              \
                                   f2tf(rb[t*4+2]), f2tf(rb[t*4+3]));             \
            *(float4*)(B_ + (br + t * 16) * 72 + bc) = v;                         \
        }                                                                         \
    } while (0)

    QKV_ISSUE_A(0, 0);
    QKV_LOAD_B(0);
    QKV_STORE_B(0);
    CP_WAIT(0);
    __syncthreads();

    #pragma unroll
    for (int ch = 0; ch < 8; ch++) {
        if (ch < 7) {
            QKV_ISSUE_A((ch + 1) & 1, (ch + 1) * 32);
            QKV_LOAD_B((ch + 1) * 32);
        }

        const float* cA = sm + (ch & 1) * QST;
        const float* cB = cA + 4608;
        #pragma unroll
        for (int kk = 0; kk < 32; kk += 8) {
            FragA a0, a1;
            wmma::load_matrix_sync(a0, cA + wm * 36 + kk, 36);
            wmma::load_matrix_sync(a1, cA + (wm + 16) * 36 + kk, 36);
            FragBR b0, b1;
            wmma::load_matrix_sync(b0, cB + kk * 72 + wn, 72);
            wmma::load_matrix_sync(b1, cB + kk * 72 + wn + 16, 72);
            wmma::mma_sync(acc[0][0], a0, b0, acc[0][0]);
            wmma::mma_sync(acc[0][1], a0, b1, acc[0][1]);
            wmma::mma_sync(acc[1][0], a1, b0, acc[1][0]);
            wmma::mma_sync(acc[1][1], a1, b1, acc[1][1]);
        }

        if (ch < 7) {
            QKV_STORE_B((ch + 1) & 1);
            CP_WAIT(0);
        }
        __syncthreads();
    }

    // epilogue: store tf32-rounded (acc + bias)
    float* sC = sm;
    #pragma unroll
    for (int i = 0; i < 2; i++)
        #pragma unroll
        for (int j = 0; j < 2; j++)
            wmma::store_matrix_sync(sC + (wm + i * 16) * 68 + wn + j * 16,
                                    acc[i][j], 68, wmma::mem_row_major);
    __syncthreads();

    const int m = tid & 127;
    const int half = tid >> 7;
    const int o = m0 + m;
    const int h = o >> 6, d = o & 63;
    const float bb = bias[o];
    int gg = n0 + half * 32;
    int bcur = gg / PPIX;
    int pcur = gg - bcur * PPIX;
    #pragma unroll
    for (int i = 0; i < 32; i++) {
        Og[(((size_t)bcur * HEADS + h) * PPIX + pcur) * DH + d] =
            f2tf(sC[m * 68 + half * 32 + i] + bb);
        if (++pcur == PPIX) { pcur = 0; bcur++; }
    }
}

// ============================================================================
// Kernel 2: attention, 32-row q-tiles, NO conversions (inputs tf32-valued).
// grid = (7, HEADS, BATCH). smem floats: Q 2304 | S 6912 | KV 14976 | sum 32
// ============================================================================
#define ATQ   0
#define ATS   2304
#define ATKV  9216
#define ATSUM 24192
#define ATTOT 24224

__global__ void __launch_bounds__(512, 2)
attn_tc()
{
    extern __shared__ float sm[];
    const int tid = threadIdx.x;
    const int w   = tid >> 5;
    const int b  = blockIdx.z;
    const int h  = blockIdx.y;
    const int q0 = blockIdx.x * 32;
    const int mrows = (q0 == 192) ? 16 : 32;

    const size_t bh = (size_t)b * HEADS + h;
    const float* Qg = g_q + bh * PD;
    const float* Kg = g_k + bh * PD;
    const float* Vg = g_v + bh * PD;

    // issue K + Q
    for (int idx = tid; idx < NPAD * 16; idx += 512) {
        int r = idx >> 4, c = (idx & 15) * 4;
        int rs = r < PPIX ? r : 0;
        cpg16z(sm + ATKV + r * 72 + c, Kg + (size_t)rs * DH + c, r < PPIX ? 16 : 0);
    }
    for (int idx = tid; idx < 32 * 16; idx += 512) {
        int r = idx >> 4, c = (idx & 15) * 4;
        int gq = q0 + r;
        int rs = gq < PPIX ? gq : 0;
        cpg16z(sm + ATQ + r * 72 + c, Qg + (size_t)rs * DH + c, gq < PPIX ? 16 : 0);
    }
    CP_COMMIT();
    CP_WAIT(0);
    __syncthreads();

    // ---- phase A: S = Q K^T (raw; scale folded into softmax) ----
    {
        const int wm = (w >> 3) * 16;
        if (wm < mrows) {
            const int g = w & 7;
            const int cnt   = (g < 5) ? 2 : 1;
            const int jbase = (g < 5) ? g * 2 : 5 + g;
            FragC acc[2];
            wmma::fill_fragment(acc[0], 0.f);
            wmma::fill_fragment(acc[1], 0.f);
            #pragma unroll
            for (int kk = 0; kk < 64; kk += 8) {
                FragA a;
                wmma::load_matrix_sync(a, sm + ATQ + wm * 72 + kk, 72);
                for (int q = 0; q < cnt; q++) {
                    FragBC bf;
                    wmma::load_matrix_sync(bf, sm + ATKV + (jbase + q) * 16 * 72 + kk, 72);
                    wmma::mma_sync(acc[q], a, bf, acc[q]);
                }
            }
            for (int q = 0; q < cnt; q++)
                wmma::store_matrix_sync(sm + ATS + wm * 216 + (jbase + q) * 16,
                                        acc[q], 216, wmma::mem_row_major);
        }
    }
    __syncthreads();

    // issue V (overwrites K) — overlaps softmax
    for (int idx = tid; idx < NPAD * 16; idx += 512) {
        int r = idx >> 4, c = (idx & 15) * 4;
        int rs = r < PPIX ? r : 0;
        cpg16z(sm + ATKV + r * 72 + c, Vg + (size_t)rs * DH + c, r < PPIX ? 16 : 0);
    }
    CP_COMMIT();

    // ---- softmax (16 lanes per row) ----
    {
        int row = tid >> 4, jl = tid & 15;
        if (row < mrows) {
            float* srow = sm + ATS + row * 216;
            float m = -1e30f;
            for (int c = jl; c < PPIX; c += 16) m = fmaxf(m, srow[c]);
            m = fmaxf(m, __shfl_xor_sync(0xffffffffu, m, 1));
            m = fmaxf(m, __shfl_xor_sync(0xffffffffu, m, 2));
            m = fmaxf(m, __shfl_xor_sync(0xffffffffu, m, 4));
            m = fmaxf(m, __shfl_xor_sync(0xffffffffu, m, 8));
            float s = 0.f;
            for (int c = jl; c < NPAD; c += 16) {
                float e = (c < PPIX) ? f2tf(__expf((srow[c] - m) * 0.125f)) : 0.f;
                srow[c] = e;
                s += e;
            }
            s += __shfl_xor_sync(0xffffffffu, s, 1);
            s += __shfl_xor_sync(0xffffffffu, s, 2);
            s += __shfl_xor_sync(0xffffffffu, s, 4);
            s += __shfl_xor_sync(0xffffffffu, s, 8);
            if (jl == 0) sm[ATSUM + row] = s;
        }
    }
    CP_WAIT(0);
    __syncthreads();

    // ---- phase C: AV = P V; 16 warps = 2(wm) x 4(wn16) x 2(K half) ----
    {
        const int kh = w >> 3;
        const int r2 = w & 7;
        const int wm = (r2 >> 2) * 16;
        const int wn = (r2 & 3) * 16;
        const bool act = (wm < mrows);
        FragC acc;
        wmma::fill_fragment(acc, 0.f);
        if (act) {
            #pragma unroll
            for (int s = 0; s < 13; s++) {
                int k = kh * 104 + s * 8;
                FragA a;
                wmma::load_matrix_sync(a, sm + ATS + wm * 216 + k, 216);
                FragBR bf;
                wmma::load_matrix_sync(bf, sm + ATKV + k * 72 + wn, 72);
                wmma::mma_sync(acc, a, bf, acc);
            }
        }
        __syncthreads();
        if (act) {
            float* buf = sm + (kh ? ATKV : ATQ);
            wmma::store_matrix_sync(buf + wm * 72 + wn, acc, 72, wmma::mem_row_major);
        }
    }
    __syncthreads();

    // epilogue: normalize, store tf32-rounded av
    float* avb = g_av + (size_t)b * (PPIX * SDIM);
    const int d = tid & 63;
    #pragma unroll
    for (int r = 0; r < 4; r++) {
        int q = (tid >> 6) + r * 8;
        int gq = q0 + q;
        if (gq < PPIX) {
            float inv = 1.f / sm[ATSUM + q];
            avb[(size_t)h * PD + (size_t)gq * DH + d] =
                f2tf((sm[ATQ + q * 72 + d] + sm[ATKV + q * 72 + d]) * inv);
        }
    }
}

// ============================================================================
// Kernel 3: output projection, global-N, pure cp.async dbuf, NO cvt.
// CTA 128(M) x 64(N). grid = (1568, 2).
// stage floats: A 128x36 = 4608 | B 64x40 = 2560 -> 7168
// ============================================================================
#define OST 7168

__global__ void __launch_bounds__(256)
outproj_tc(const float* __restrict__ bo, float* __restrict__ out)
{
    extern __shared__ float sm[];
    const int tid = threadIdx.x;
    const int w   = tid >> 5;
    const int n0  = blockIdx.x * 64;
    const int m0  = blockIdx.y * 128;

    const float* W = g_wc[3];
    const int wm = (w >> 1) * 32;
    const int wn = (w & 1) * 32;

    const int ar = tid >> 3, ac = (tid & 7) * 4;   // A: 4 passes of 32 rows
    const int br = tid >> 3, bc = (tid & 7) * 4;   // B: 2 passes of 32 rows

    FragC acc[2][2];
    #pragma unroll
    for (int i = 0; i < 2; i++)
        #pragma unroll
        for (int j = 0; j < 2; j++) wmma::fill_fragment(acc[i][j], 0.f);

    #define OUT_ISSUE(s, k0) do {                                                 \
        float* A_ = sm + (s) * OST;                                               \
        float* B_ = A_ + 4608;                                                    \
        _Pragma("unroll")                                                         \
        for (int t = 0; t < 4; t++)                                               \
            cpa16(A_ + (ar + t * 32) * 36 + ac,                                   \
                  W + (size_t)(m0 + ar + t * 32) * SDIM + (k0) + ac);             \
        _Pragma("unroll")                                                         \
        for (int t = 0; t < 2; t++)                                               \
            cpa16(B_ + (br + t * 32) * 40 + bc,                                   \
                  g_av + (size_t)(n0 + br + t * 32) * SDIM + (k0) + bc);          \
        CP_COMMIT();                                                              \
    } while (0)

    OUT_ISSUE(0, 0);

    #pragma unroll
    for (int ch = 0; ch < 8; ch++) {
        if (ch < 7) {
            OUT_ISSUE((ch + 1) & 1, (ch + 1) * 32);
            CP_WAIT(1);
        } else {
            CP_WAIT(0);
        }
        __syncthreads();

        const float* cA = sm + (ch & 1) * OST;
        const float* cB = cA + 4608;
        #pragma unroll
        for (int kk = 0; kk < 32; kk += 8) {
            FragA a0, a1;
            wmma::load_matrix_sync(a0, cA + wm * 36 + kk, 36);
            wmma::load_matrix_sync(a1, cA + (wm + 16) * 36 + kk, 36);
            FragBC b0, b1;
            wmma::load_matrix_sync(b0, cB + wn * 40 + kk, 40);
            wmma::load_matrix_sync(b1, cB + (wn + 16) * 40 + kk, 40);
            wmma::mma_sync(acc[0][0], a0, b0, acc[0][0]);
            wmma::mma_sync(acc[0][1], a0, b1, acc[0][1]);
            wmma::mma_sync(acc[1][0], a1, b0, acc[1][0]);
            wmma::mma_sync(acc[1][1], a1, b1, acc[1][1]);
        }
        __syncthreads();
    }

    float* sC = sm;
    #pragma unroll
    for (int i = 0; i < 2; i++)
        #pragma unroll
        for (int j = 0; j < 2; j++)
            wmma::store_matrix_sync(sC + (wm + i * 16) * 68 + wn + j * 16,
                                    acc[i][j], 68, wmma::mem_row_major);
    __syncthreads();

    const int m = tid >> 1;
    const int half = tid & 1;
    const int o = m0 + m;
    const float bb = bo[o];
    int gg = n0 + half * 32;
    int bcur = gg / PPIX;
    int pcur = gg - bcur * PPIX;
    #pragma unroll
    for (int i = 0; i < 32; i++) {
        out[((size_t)bcur * SDIM + o) * PPIX + pcur] =
            sC[m * 68 + half * 32 + i] + bb;
        if (++pcur == PPIX) { pcur = 0; bcur++; }
    }
}

// ============================================================================
extern "C" void kernel_launch(void* const* d_in, const int* in_sizes, int n_in,
                              void* d_out, int out_size)
{
    const float* x  = (const float*)d_in[0];
    const float* wq = (const float*)d_in[1];
    const float* bq = (const float*)d_in[2];
    const float* wk = (const float*)d_in[3];
    const float* bk = (const float*)d_in[4];
    const float* wv = (const float*)d_in[5];
    const float* bv = (const float*)d_in[6];
    const float* wo = (const float*)d_in[7];
    const float* bo = (const float*)d_in[8];
    float* out = (float*)d_out;

    cvt_w<<<SDIM * SDIM / 256, 256>>>(wq, wk, wv, wo);

    const int qkv_smem = 2 * QST * 4;           // 55,296
    cudaFuncSetAttribute(qkv_tc, cudaFuncAttributeMaxDynamicSharedMemorySize, qkv_smem);
    qkv_tc<<<dim3(NTILES, 6), 256, qkv_smem>>>(x, bq, bk, bv);

    const int attn_smem = ATTOT * 4;            // 96,896
    cudaFuncSetAttribute(attn_tc, cudaFuncAttributeMaxDynamicSharedMemorySize, attn_smem);
    attn_tc<<<dim3(7, HEADS, BATCH), 512, attn_smem>>>();

    const int out_smem = 2 * OST * 4;           // 57,344
    cudaFuncSetAttribute(outproj_tc, cudaFuncAttributeMaxDynamicSharedMemorySize, out_smem);
    outproj_tc<<<dim3(NTILES, 2), 256, out_smem>>>(bo, out);
}

// round 10
// speedup vs baseline: 1.1539x; 1.0634x over previous
#include <cuda_runtime.h>
#include <cstdint>
#include <math.h>
#include <mma.h>

using namespace nvcuda;

#define BATCH 512
#define HEADS 4
#define SDIM  256
#define PPIX  196
#define DH    64
#define PD    (PPIX * DH)
#define NPAD  208
#define NT128 784              // 100352 / 128

// ---------------- scratch ----------------
#define QKV_ELEMS (BATCH * HEADS * PPIX * DH)
#define X_ELEMS   (BATCH * SDIM * PPIX)
__device__ float g_q[QKV_ELEMS];
__device__ float g_k[QKV_ELEMS];
__device__ float g_v[QKV_ELEMS];
__device__ float g_av[BATCH * PPIX * SDIM];   // flat [g][c], tf32-valued
__device__ float g_wc[4][SDIM * SDIM];        // tf32-rounded weights
__device__ float g_xc[X_ELEMS];               // tf32-rounded x

__device__ __forceinline__ float f2tf(float v) {
    uint32_t u;
    asm("cvt.rna.tf32.f32 %0, %1;" : "=r"(u) : "f"(v));
    return __uint_as_float(u);
}

__device__ __forceinline__ void cpa16(float* dst, const float* src) {
    uint32_t d = (uint32_t)__cvta_generic_to_shared(dst);
    asm volatile("cp.async.cg.shared.global [%0], [%1], 16;" :: "r"(d), "l"(src) : "memory");
}
__device__ __forceinline__ void cpg16z(float* dst, const float* src, int bytes) {
    uint32_t d = (uint32_t)__cvta_generic_to_shared(dst);
    asm volatile("cp.async.cg.shared.global [%0], [%1], 16, %2;"
                 :: "r"(d), "l"(src), "r"(bytes) : "memory");
}
#define CP_COMMIT() asm volatile("cp.async.commit_group;" ::: "memory")
#define CP_WAIT(n)  asm volatile("cp.async.wait_group %0;" :: "n"(n) : "memory")

typedef wmma::fragment<wmma::matrix_a, 16, 16, 8, wmma::precision::tf32, wmma::row_major> FragA;
typedef wmma::fragment<wmma::matrix_b, 16, 16, 8, wmma::precision::tf32, wmma::row_major> FragBR;
typedef wmma::fragment<wmma::matrix_b, 16, 16, 8, wmma::precision::tf32, wmma::col_major> FragBC;
typedef wmma::fragment<wmma::accumulator, 16, 16, 8, float> FragC;

// ============================================================================
// Kernel 0a/0b: round weights + x to tf32 once.
// ============================================================================
__global__ void cvt_w(const float* __restrict__ wq, const float* __restrict__ wk,
                      const float* __restrict__ wv, const float* __restrict__ wo)
{
    int i = blockIdx.x * 256 + threadIdx.x;
    g_wc[0][i] = f2tf(wq[i]);
    g_wc[1][i] = f2tf(wk[i]);
    g_wc[2][i] = f2tf(wv[i]);
    g_wc[3][i] = f2tf(wo[i]);
}

__global__ void cvt_x(const float* __restrict__ x)
{
    size_t i = (size_t)blockIdx.x * 256 + threadIdx.x;   // float4 index
    float4 v = ((const float4*)x)[i];
    ((float4*)g_xc)[i] = make_float4(f2tf(v.x), f2tf(v.y), f2tf(v.z), f2tf(v.w));
}

// ============================================================================
// Kernel 1: QKV projection, global-N. CTA 128(M) x 128(N). grid (784, 6).
// Pure cp.async (pre-rounded W and x); warp tile 32x64 (8 warps = 4m x 2n).
// stage floats: A 128x36 = 4608 | B 32x132 = 4224 -> 8832
// ============================================================================
#define QST 8832

__global__ void __launch_bounds__(256, 2)
qkv_tc(const float* __restrict__ bq, const float* __restrict__ bk,
       const float* __restrict__ bv)
{
    extern __shared__ float sm[];
    const int tid = threadIdx.x;
    const int w   = tid >> 5;
    const int n0  = blockIdx.x * 128;
    const int ws  = blockIdx.y >> 1;
    const int m0  = (blockIdx.y & 1) * 128;

    const float* W    = g_wc[ws];
    const float* bias = (ws == 0) ? bq : (ws == 1) ? bk : bv;
    float* Og         = (ws == 0) ? g_q : (ws == 1) ? g_k : g_v;

    const int wm = (w & 3) * 32;
    const int wn = (w >> 2) * 64;

    // A fill: 128x32, 4 passes. B fill: 32x128, 4 passes (chunk col fixed/thread).
    const int ar = tid >> 3, ac = (tid & 7) * 4;
    const int br = tid >> 5, bc = (tid & 31) * 4;
    const int g0   = n0 + bc;
    const int b0c  = g0 / PPIX;
    const int p0c  = g0 - b0c * PPIX;
    const bool cross = (p0c > PPIX - 4);
    const float* xb0 = g_xc + (size_t)b0c * (SDIM * PPIX) + p0c;

    FragC acc[2][4];
    #pragma unroll
    for (int i = 0; i < 2; i++)
        #pragma unroll
        for (int j = 0; j < 4; j++) wmma::fill_fragment(acc[i][j], 0.f);

    #define QKV_ISSUE(s, k0) do {                                                 \
        float* A_ = sm + (s) * QST;                                               \
        float* B_ = A_ + 4608;                                                    \
        _Pragma("unroll")                                                         \
        for (int t = 0; t < 4; t++)                                               \
            cpa16(A_ + (ar + t * 32) * 36 + ac,                                   \
                  W + (size_t)(m0 + ar + t * 32) * SDIM + (k0) + ac);             \
        if (!cross) {                                                             \
            _Pragma("unroll")                                                     \
            for (int t = 0; t < 4; t++)                                           \
                cpa16(B_ + (br + t * 8) * 132 + bc,                               \
                      xb0 + (size_t)((k0) + br + t * 8) * PPIX);                  \
        } else {                                                                  \
            _Pragma("unroll")                                                     \
            for (int t = 0; t < 4; t++) {                                         \
                int krow = (k0) + br + t * 8;                                     \
                float4 v;                                                         \
                _Pragma("unroll")                                                 \
                for (int e = 0; e < 4; e++) {                                     \
                    int g = g0 + e;                                               \
                    int bb = g / PPIX, pp = g - bb * PPIX;                        \
                    ((float*)&v)[e] =                                             \
                        g_xc[((size_t)bb * SDIM + krow) * PPIX + pp];             \
                }                                                                 \
                *(float4*)(B_ + (br + t * 8) * 132 + bc) = v;                     \
            }                                                                     \
        }                                                                         \
        CP_COMMIT();                                                              \
    } while (0)

    QKV_ISSUE(0, 0);

    #pragma unroll
    for (int ch = 0; ch < 8; ch++) {
        if (ch < 7) {
            QKV_ISSUE((ch + 1) & 1, (ch + 1) * 32);
            CP_WAIT(1);
        } else {
            CP_WAIT(0);
        }
        __syncthreads();

        const float* cA = sm + (ch & 1) * QST;
        const float* cB = cA + 4608;
        #pragma unroll
        for (int kk = 0; kk < 32; kk += 8) {
            FragA a0, a1;
            wmma::load_matrix_sync(a0, cA + wm * 36 + kk, 36);
            wmma::load_matrix_sync(a1, cA + (wm + 16) * 36 + kk, 36);
            #pragma unroll
            for (int j = 0; j < 4; j++) {
                FragBR bf;
                wmma::load_matrix_sync(bf, cB + kk * 132 + wn + j * 16, 132);
                wmma::mma_sync(acc[0][j], a0, bf, acc[0][j]);
                wmma::mma_sync(acc[1][j], a1, bf, acc[1][j]);
            }
        }
        __syncthreads();
    }

    // epilogue: sC 128x132 (reuse both stages)
    float* sC = sm;
    #pragma unroll
    for (int i = 0; i < 2; i++)
        #pragma unroll
        for (int j = 0; j < 4; j++)
            wmma::store_matrix_sync(sC + (wm + i * 16) * 132 + wn + j * 16,
                                    acc[i][j], 132, wmma::mem_row_major);
    __syncthreads();

    // write: thread = (column, m-half). 64 consecutive d per thread -> float4.
    const int col  = tid >> 1;
    const int half = tid & 1;
    const int gg = n0 + col;
    const int bcur = gg / PPIX;
    const int pcur = gg - bcur * PPIX;
    const int h = (m0 >> 6) + half;
    float* ob = Og + (((size_t)bcur * HEADS + h) * PPIX + pcur) * DH;
    const float* bptr = bias + m0 + half * 64;
    const float* cptr = sC + (size_t)(half * 64) * 132 + col;
    #pragma unroll
    for (int i = 0; i < 16; i++) {
        float4 v;
        v.x = f2tf(cptr[(i*4+0) * 132] + bptr[i*4+0]);
        v.y = f2tf(cptr[(i*4+1) * 132] + bptr[i*4+1]);
        v.z = f2tf(cptr[(i*4+2) * 132] + bptr[i*4+2]);
        v.w = f2tf(cptr[(i*4+3) * 132] + bptr[i*4+3]);
        *(float4*)(ob + i * 4) = v;
    }
}

// ============================================================================
// Kernel 2: attention, 32-row q-tiles, cvt-free (inputs tf32-valued).
// grid = (7, HEADS, BATCH). smem floats: Q 2304 | S 6912 | KV 14976 | sum 32
// ============================================================================
#define ATQ   0
#define ATS   2304
#define ATKV  9216
#define ATSUM 24192
#define ATTOT 24224

__global__ void __launch_bounds__(512, 2)
attn_tc()
{
    extern __shared__ float sm[];
    const int tid = threadIdx.x;
    const int w   = tid >> 5;
    const int b  = blockIdx.z;
    const int h  = blockIdx.y;
    const int q0 = blockIdx.x * 32;
    const int mrows = (q0 == 192) ? 16 : 32;

    const size_t bh = (size_t)b * HEADS + h;
    const float* Qg = g_q + bh * PD;
    const float* Kg = g_k + bh * PD;
    const float* Vg = g_v + bh * PD;

    for (int idx = tid; idx < NPAD * 16; idx += 512) {
        int r = idx >> 4, c = (idx & 15) * 4;
        int rs = r < PPIX ? r : 0;
        cpg16z(sm + ATKV + r * 72 + c, Kg + (size_t)rs * DH + c, r < PPIX ? 16 : 0);
    }
    for (int idx = tid; idx < 32 * 16; idx += 512) {
        int r = idx >> 4, c = (idx & 15) * 4;
        int gq = q0 + r;
        int rs = gq < PPIX ? gq : 0;
        cpg16z(sm + ATQ + r * 72 + c, Qg + (size_t)rs * DH + c, gq < PPIX ? 16 : 0);
    }
    CP_COMMIT();
    CP_WAIT(0);
    __syncthreads();

    // phase A: S = Q K^T
    {
        const int wm = (w >> 3) * 16;
        if (wm < mrows) {
            const int g = w & 7;
            const int cnt   = (g < 5) ? 2 : 1;
            const int jbase = (g < 5) ? g * 2 : 5 + g;
            FragC acc[2];
            wmma::fill_fragment(acc[0], 0.f);
            wmma::fill_fragment(acc[1], 0.f);
            #pragma unroll
            for (int kk = 0; kk < 64; kk += 8) {
                FragA a;
                wmma::load_matrix_sync(a, sm + ATQ + wm * 72 + kk, 72);
                for (int q = 0; q < cnt; q++) {
                    FragBC bf;
                    wmma::load_matrix_sync(bf, sm + ATKV + (jbase + q) * 16 * 72 + kk, 72);
                    wmma::mma_sync(acc[q], a, bf, acc[q]);
                }
            }
            for (int q = 0; q < cnt; q++)
                wmma::store_matrix_sync(sm + ATS + wm * 216 + (jbase + q) * 16,
                                        acc[q], 216, wmma::mem_row_major);
        }
    }
    __syncthreads();

    // issue V (overwrites K)
    for (int idx = tid; idx < NPAD * 16; idx += 512) {
        int r = idx >> 4, c = (idx & 15) * 4;
        int rs = r < PPIX ? r : 0;
        cpg16z(sm + ATKV + r * 72 + c, Vg + (size_t)rs * DH + c, r < PPIX ? 16 : 0);
    }
    CP_COMMIT();

    // softmax
    {
        int row = tid >> 4, jl = tid & 15;
        if (row < mrows) {
            float* srow = sm + ATS + row * 216;
            float m = -1e30f;
            for (int c = jl; c < PPIX; c += 16) m = fmaxf(m, srow[c]);
            m = fmaxf(m, __shfl_xor_sync(0xffffffffu, m, 1));
            m = fmaxf(m, __shfl_xor_sync(0xffffffffu, m, 2));
            m = fmaxf(m, __shfl_xor_sync(0xffffffffu, m, 4));
            m = fmaxf(m, __shfl_xor_sync(0xffffffffu, m, 8));
            float s = 0.f;
            for (int c = jl; c < NPAD; c += 16) {
                float e = (c < PPIX) ? f2tf(__expf((srow[c] - m) * 0.125f)) : 0.f;
                srow[c] = e;
                s += e;
            }
            s += __shfl_xor_sync(0xffffffffu, s, 1);
            s += __shfl_xor_sync(0xffffffffu, s, 2);
            s += __shfl_xor_sync(0xffffffffu, s, 4);
            s += __shfl_xor_sync(0xffffffffu, s, 8);
            if (jl == 0) sm[ATSUM + row] = s;
        }
    }
    CP_WAIT(0);
    __syncthreads();

    // phase C: AV = P V
    {
        const int kh = w >> 3;
        const int r2 = w & 7;
        const int wm = (r2 >> 2) * 16;
        const int wn = (r2 & 3) * 16;
        const bool act = (wm < mrows);
        FragC acc;
        wmma::fill_fragment(acc, 0.f);
        if (act) {
            #pragma unroll
            for (int s = 0; s < 13; s++) {
                int k = kh * 104 + s * 8;
                FragA a;
                wmma::load_matrix_sync(a, sm + ATS + wm * 216 + k, 216);
                FragBR bf;
                wmma::load_matrix_sync(bf, sm + ATKV + k * 72 + wn, 72);
                wmma::mma_sync(acc, a, bf, acc);
            }
        }
        __syncthreads();
        if (act) {
            float* buf = sm + (kh ? ATKV : ATQ);
            wmma::store_matrix_sync(buf + wm * 72 + wn, acc, 72, wmma::mem_row_major);
        }
    }
    __syncthreads();

    float* avb = g_av + (size_t)b * (PPIX * SDIM);
    const int d = tid & 63;
    #pragma unroll
    for (int r = 0; r < 4; r++) {
        int q = (tid >> 6) + r * 8;
        int gq = q0 + q;
        if (gq < PPIX) {
            float inv = 1.f / sm[ATSUM + q];
            avb[(size_t)h * PD + (size_t)gq * DH + d] =
                f2tf((sm[ATQ + q * 72 + d] + sm[ATKV + q * 72 + d]) * inv);
        }
    }
}

// ============================================================================
// Kernel 3: output projection, global-N. CTA 128(M) x 128(N). grid (784, 2).
// Pure cp.async, no cvt. stage floats: A 128x36 = 4608 | B 128x40 = 5120
// ============================================================================
#define OST 9728

__global__ void __launch_bounds__(256, 2)
outproj_tc(const float* __restrict__ bo, float* __restrict__ out)
{
    extern __shared__ float sm[];
    const int tid = threadIdx.x;
    const int w   = tid >> 5;
    const int n0  = blockIdx.x * 128;
    const int m0  = blockIdx.y * 128;

    const float* W = g_wc[3];
    const int wm = (w & 3) * 32;
    const int wn = (w >> 2) * 64;

    const int ar = tid >> 3, ac = (tid & 7) * 4;   // A: 4 passes of 32 rows
    const int br = tid >> 3, bc = (tid & 7) * 4;   // B: 4 passes of 32 rows

    FragC acc[2][4];
    #pragma unroll
    for (int i = 0; i < 2; i++)
        #pragma unroll
        for (int j = 0; j < 4; j++) wmma::fill_fragment(acc[i][j], 0.f);

    #define OUT_ISSUE(s, k0) do {                                                 \
        float* A_ = sm + (s) * OST;                                               \
        float* B_ = A_ + 4608;                                                    \
        _Pragma("unroll")                                                         \
        for (int t = 0; t < 4; t++)                                               \
            cpa16(A_ + (ar + t * 32) * 36 + ac,                                   \
                  W + (size_t)(m0 + ar + t * 32) * SDIM + (k0) + ac);             \
        _Pragma("unroll")                                                         \
        for (int t = 0; t < 4; t++)                                               \
            cpa16(B_ + (br + t * 32) * 40 + bc,                                   \
                  g_av + (size_t)(n0 + br + t * 32) * SDIM + (k0) + bc);          \
        CP_COMMIT();                                                              \
    } while (0)

    OUT_ISSUE(0, 0);

    #pragma unroll
    for (int ch = 0; ch < 8; ch++) {
        if (ch < 7) {
            OUT_ISSUE((ch + 1) & 1, (ch + 1) * 32);
            CP_WAIT(1);
        } else {
            CP_WAIT(0);
        }
        __syncthreads();

        const float* cA = sm + (ch & 1) * OST;
        const float* cB = cA + 4608;
        #pragma unroll
        for (int kk = 0; kk < 32; kk += 8) {
            FragA a0, a1;
            wmma::load_matrix_sync(a0, cA + wm * 36 + kk, 36);
            wmma::load_matrix_sync(a1, cA + (wm + 16) * 36 + kk, 36);
            #pragma unroll
            for (int j = 0; j < 4; j++) {
                FragBC bf;
                wmma::load_matrix_sync(bf, cB + (wn + j * 16) * 40 + kk, 40);
                wmma::mma_sync(acc[0][j], a0, bf, acc[0][j]);
                wmma::mma_sync(acc[1][j], a1, bf, acc[1][j]);
            }
        }
        __syncthreads();
    }

    float* sC = sm;
    #pragma unroll
    for (int i = 0; i < 2; i++)
        #pragma unroll
        for (int j = 0; j < 4; j++)
            wmma::store_matrix_sync(sC + (wm + i * 16) * 132 + wn + j * 16,
                                    acc[i][j], 132, wmma::mem_row_major);
    __syncthreads();

    // write: thread = (m row, col-half of 64); walk p with boundary wrap
    const int m = tid >> 1;
    const int half = tid & 1;
    const int o = m0 + m;
    const float bb = bo[o];
    int gg = n0 + half * 64;
    int bcur = gg / PPIX;
    int pcur = gg - bcur * PPIX;
    const float* crow = sC + (size_t)m * 132 + half * 64;
    #pragma unroll
    for (int i = 0; i < 64; i++) {
        out[((size_t)bcur * SDIM + o) * PPIX + pcur] = crow[i] + bb;
        if (++pcur == PPIX) { pcur = 0; bcur++; }
    }
}

// ============================================================================
extern "C" void kernel_launch(void* const* d_in, const int* in_sizes, int n_in,
                              void* d_out, int out_size)
{
    const float* x  = (const float*)d_in[0];
    const float* wq = (const float*)d_in[1];
    const float* bq = (const float*)d_in[2];
    const float* wk = (const float*)d_in[3];
    const float* bk = (const float*)d_in[4];
    const float* wv = (const float*)d_in[5];
    const float* bv = (const float*)d_in[6];
    const float* wo = (const float*)d_in[7];
    const float* bo = (const float*)d_in[8];
    float* out = (float*)d_out;

    cvt_w<<<SDIM * SDIM / 256, 256>>>(wq, wk, wv, wo);
    cvt_x<<<X_ELEMS / 1024, 256>>>(x);

    const int qkv_smem = 2 * QST * 4;           // 70,656
    cudaFuncSetAttribute(qkv_tc, cudaFuncAttributeMaxDynamicSharedMemorySize, qkv_smem);
    qkv_tc<<<dim3(NT128, 6), 256, qkv_smem>>>(bq, bk, bv);

    const int attn_smem = ATTOT * 4;            // 96,896
    cudaFuncSetAttribute(attn_tc, cudaFuncAttributeMaxDynamicSharedMemorySize, attn_smem);
    attn_tc<<<dim3(7, HEADS, BATCH), 512, attn_smem>>>();

    const int out_smem = 2 * OST * 4;           // 77,824
    cudaFuncSetAttribute(outproj_tc, cudaFuncAttributeMaxDynamicSharedMemorySize, out_smem);
    outproj_tc<<<dim3(NT128, 2), 256, out_smem>>>(bo, out);
}